// round 2
// baseline (speedup 1.0000x reference)
#include <cuda_runtime.h>
#include <math_constants.h>

#define GROUPS 64
#define DIM    256
#define NROWS  1048576
#define NCTA   148
#define TPB    256
#define UNROLL 16

// ---------------- global scratch (no allocation allowed) ----------------
__device__ unsigned gMaxU[GROUPS * DIM];
__device__ unsigned gMinU[GROUPS * DIM];
__device__ float    gSum [GROUPS * DIM];
__device__ unsigned gCnt [GROUPS];

// monotonic float<->uint encoding (order-preserving for all finite floats)
__device__ __forceinline__ unsigned enc(float v) {
    int i = __float_as_int(v);
    return (i >= 0) ? ((unsigned)i | 0x80000000u) : ~(unsigned)i;
}
__device__ __forceinline__ float dec(unsigned u) {
    return (u & 0x80000000u) ? __int_as_float((int)(u ^ 0x80000000u))
                             : __int_as_float((int)~u);
}

// ---------------- kernel 0: reset global scratch (runs every replay) ---
__global__ void k_init() {
    int i = blockIdx.x * blockDim.x + threadIdx.x;
    if (i < GROUPS * DIM) {
        gMaxU[i] = 0u;            // enc(-inf) = 0x007FFFFF > 0, so 0 never survives
        gMinU[i] = 0xFFFFFFFFu;
        gSum [i] = 0.0f;
    }
    if (i < GROUPS) gCnt[i] = 0u;
}

// ---------------- kernel 1: group histogram (counts for the mean) ------
__global__ void k_count(const int* __restrict__ gi) {
    __shared__ unsigned h[GROUPS];
    int t = threadIdx.x;
    if (t < GROUPS) h[t] = 0u;
    __syncthreads();
    for (int i = blockIdx.x * blockDim.x + t; i < NROWS; i += gridDim.x * blockDim.x)
        atomicAdd(&h[gi[i]], 1u);
    __syncthreads();
    if (t < GROUPS) atomicAdd(&gCnt[t], h[t]);
}

// ---------------- kernel 2: main streaming segment reduction ----------
// One CTA = 256 threads, thread t exclusively owns column t of the shared
// accumulators -> race-free without atomics. All 8 warps process the same
// row (warp w covers cols 32w..32w+31). Rows interleaved over 148 CTAs.
extern __shared__ float smem_dyn[];

__global__ void __launch_bounds__(TPB, 1) k_main(const float* __restrict__ f,
                                                 const int* __restrict__ gi) {
    float* sMax = smem_dyn;                    // [GROUPS*DIM]
    float* sMin = sMax + GROUPS * DIM;         // [GROUPS*DIM]
    float* sSum = sMin + GROUPS * DIM;         // [GROUPS*DIM]

    const int tid = threadIdx.x;
    const int bid = blockIdx.x;

    for (int i = tid; i < GROUPS * DIM; i += TPB) {
        sMax[i] = -CUDART_INF_F;
        sMin[i] =  CUDART_INF_F;
        sSum[i] =  0.0f;
    }
    __syncthreads();

    // rows handled by this CTA: r = bid + j*NCTA, j = 0..nIter-1
    const int nIter = (NROWS - bid + NCTA - 1) / NCTA;
    const int full  = nIter & ~(UNROLL - 1);
    const int base  = bid * DIM + tid;         // max index < 2^28, int is fine
    const int estep = NCTA * DIM;              // element stride per row step

    int it = 0;
    for (; it < full; it += UNROLL) {
        float v[UNROLL];
        int   g[UNROLL];
        const int o  = base + it * estep;
        const int ro = bid  + it * NCTA;
#pragma unroll
        for (int u = 0; u < UNROLL; u++) {
            v[u] = __ldg(&f[o + u * estep]);
            g[u] = __ldg(&gi[ro + u * NCTA]);
        }
#pragma unroll
        for (int u = 0; u < UNROLL; u++) {
            const int a = g[u] * DIM + tid;
            const float val = v[u];
            const float m0 = sMax[a];
            const float m1 = sMin[a];
            const float s0 = sSum[a];
            sMax[a] = fmaxf(m0, val);
            sMin[a] = fminf(m1, val);
            sSum[a] = s0 + val;
        }
    }
    for (; it < nIter; ++it) {
        const float val = f[base + it * estep];
        const int a = gi[bid + it * NCTA] * DIM + tid;
        sMax[a] = fmaxf(sMax[a], val);
        sMin[a] = fminf(sMin[a], val);
        sSum[a] = sSum[a] + val;
    }
    __syncthreads();

    // merge CTA partials into global scratch
    for (int i = tid; i < GROUPS * DIM; i += TPB) {
        atomicMax(&gMaxU[i], enc(sMax[i]));
        atomicMin(&gMinU[i], enc(sMin[i]));
        atomicAdd(&gSum[i], sSum[i]);
    }
}

// ---------------- kernel 3: finalize -> out[g][0:256]=max, [256:512]=min,
// [512:768]=mean ---------------------------------------------------------
__global__ void k_final(float* __restrict__ out) {
    const int g = blockIdx.x;
    const int c = threadIdx.x;
    const int i = g * DIM + c;
    out[g * 3 * DIM + c]           = dec(gMaxU[i]);
    out[g * 3 * DIM + DIM + c]     = dec(gMinU[i]);
    out[g * 3 * DIM + 2 * DIM + c] = gSum[i] / (float)gCnt[g];
}

extern "C" void kernel_launch(void* const* d_in, const int* in_sizes, int n_in,
                              void* d_out, int out_size) {
    const float* f  = (const float*)d_in[0];   // features [N, D] f32
    const int*   gi = (const int*)d_in[1];     // group_index [N] i32
    float* out = (float*)d_out;                // [64, 768] f32

    const int smem_bytes = 3 * GROUPS * DIM * (int)sizeof(float);  // 196608
    cudaFuncSetAttribute(k_main, cudaFuncAttributeMaxDynamicSharedMemorySize,
                         smem_bytes);

    k_init <<<(GROUPS * DIM + 255) / 256, 256>>>();
    k_count<<<148, 256>>>(gi);
    k_main <<<NCTA, TPB, smem_bytes>>>(f, gi);
    k_final<<<GROUPS, DIM>>>(out);
}

// round 3
// speedup vs baseline: 2.4452x; 2.4452x over previous
#include <cuda_runtime.h>
#include <math_constants.h>

#define GROUPS 64
#define DIM    256
#define NROWS  1048576
#define CAP    20480          // per-group perm capacity (mean 16384, +32 sigma)
#define CPG    7              // chunks (CTAs) per group in main kernel
#define SCTA   148
#define CHUNK  ((NROWS + SCTA - 1) / SCTA)   // 7086
#define TPB    256

// ---------------- global scratch (no allocation allowed) ----------------
__device__ int      gPerm[GROUPS * CAP];     // binned row indices
__device__ int      gOffset[GROUPS];         // scatter cursors / final counts
__device__ unsigned gMaxU[GROUPS * DIM];
__device__ unsigned gMinU[GROUPS * DIM];
__device__ float    gSum [GROUPS * DIM];

// monotonic float<->uint encoding (order-preserving over all floats)
__device__ __forceinline__ unsigned enc(float v) {
    int i = __float_as_int(v);
    return (i >= 0) ? ((unsigned)i | 0x80000000u) : ~(unsigned)i;
}
__device__ __forceinline__ float dec(unsigned u) {
    return (u & 0x80000000u) ? __int_as_float((int)(u ^ 0x80000000u))
                             : __int_as_float((int)~u);
}

// ---------------- kernel 0: reset scratch (graph replays need this) ----
__global__ void k_init() {
    int i = blockIdx.x * blockDim.x + threadIdx.x;
    if (i < GROUPS * DIM) {
        gMaxU[i] = 0u;              // enc(-inf) = 0x007FFFFF >= 0, identity ok
        gMinU[i] = 0xFFFFFFFFu;
        gSum [i] = 0.0f;
    }
    if (i < GROUPS) gOffset[i] = i * CAP;
}

// ---------------- kernel 1: counting-sort scatter (bin rows by group) --
__global__ void __launch_bounds__(TPB) k_scatter(const int* __restrict__ gi) {
    __shared__ int sg[CHUNK];       // cached group ids for this CTA's chunk
    __shared__ int sBase[GROUPS];
    __shared__ int sCur[GROUPS];

    const int tid   = threadIdx.x;
    const int start = blockIdx.x * CHUNK;
    const int n     = min(CHUNK, NROWS - start);

    if (tid < GROUPS) sCur[tid] = 0;
    __syncthreads();

    for (int i = tid; i < n; i += TPB) {
        int g = __ldg(&gi[start + i]);
        sg[i] = g;
        atomicAdd(&sCur[g], 1);
    }
    __syncthreads();

    if (tid < GROUPS) {
        sBase[tid] = atomicAdd(&gOffset[tid], sCur[tid]);  // reserve block
        sCur[tid]  = 0;
    }
    __syncthreads();

    for (int i = tid; i < n; i += TPB) {
        int g = sg[i];
        int p = sBase[g] + atomicAdd(&sCur[g], 1);
        gPerm[p] = start + i;
    }
}

// ---------------- kernel 2: register-accumulator segment reduction -----
// CTA (g, c): group g = bid/CPG, chunk c = bid%CPG. Thread t owns column t.
// Hot loop: uniform perm load + coalesced row-segment load + 3 FP ops.
// No shared memory, no atomics, no aliasing -> fully pipelined.
__global__ void __launch_bounds__(TPB) k_main(const float* __restrict__ f) {
    const int g = blockIdx.x / CPG;
    const int c = blockIdx.x % CPG;
    const int t = threadIdx.x;

    const int cnt = gOffset[g] - g * CAP;          // group row count
    const int per = (cnt + CPG - 1) / CPG;
    const int s   = c * per;
    const int e   = min(s + per, cnt);
    const int* __restrict__ perm = &gPerm[g * CAP];

    float mx = -CUDART_INF_F, mn = CUDART_INF_F, sm = 0.0f;

    int it = s;
    const int full = s + ((e - s) & ~7);
    for (; it < full; it += 8) {
        int   r[8];
        float v[8];
#pragma unroll
        for (int u = 0; u < 8; u++) r[u] = __ldg(&perm[it + u]);
#pragma unroll
        for (int u = 0; u < 8; u++) v[u] = __ldg(&f[r[u] * DIM + t]);

        // tree-combine the 8 values, then one accumulator update each
        float a0 = fmaxf(v[0], v[1]), a1 = fmaxf(v[2], v[3]);
        float a2 = fmaxf(v[4], v[5]), a3 = fmaxf(v[6], v[7]);
        mx = fmaxf(mx, fmaxf(fmaxf(a0, a1), fmaxf(a2, a3)));

        float b0 = fminf(v[0], v[1]), b1 = fminf(v[2], v[3]);
        float b2 = fminf(v[4], v[5]), b3 = fminf(v[6], v[7]);
        mn = fminf(mn, fminf(fminf(b0, b1), fminf(b2, b3)));

        float s0 = v[0] + v[1], s1 = v[2] + v[3];
        float s2 = v[4] + v[5], s3 = v[6] + v[7];
        sm += (s0 + s1) + (s2 + s3);
    }
    for (; it < e; ++it) {
        float v = __ldg(&f[__ldg(&perm[it]) * DIM + t]);
        mx = fmaxf(mx, v);
        mn = fminf(mn, v);
        sm += v;
    }

    const int a = g * DIM + t;
    atomicMax(&gMaxU[a], enc(mx));
    atomicMin(&gMinU[a], enc(mn));
    atomicAdd(&gSum[a], sm);
}

// ---------------- kernel 3: finalize [G, 768] = [max || min || mean] ----
__global__ void k_final(float* __restrict__ out) {
    const int g = blockIdx.x;
    const int c = threadIdx.x;
    const int i = g * DIM + c;
    const float cnt = (float)(gOffset[g] - g * CAP);
    out[g * 3 * DIM + c]           = dec(gMaxU[i]);
    out[g * 3 * DIM + DIM + c]     = dec(gMinU[i]);
    out[g * 3 * DIM + 2 * DIM + c] = gSum[i] / cnt;
}

extern "C" void kernel_launch(void* const* d_in, const int* in_sizes, int n_in,
                              void* d_out, int out_size) {
    const float* f  = (const float*)d_in[0];   // features [N, D] f32
    const int*   gi = (const int*)d_in[1];     // group_index [N] i32
    float* out = (float*)d_out;                // [64, 768] f32

    k_init   <<<(GROUPS * DIM + 255) / 256, 256>>>();
    k_scatter<<<SCTA, TPB>>>(gi);
    k_main   <<<GROUPS * CPG, TPB>>>(f);
    k_final  <<<GROUPS, DIM>>>(out);
}

// round 4
// speedup vs baseline: 4.6067x; 1.8840x over previous
#include <cuda_runtime.h>
#include <math_constants.h>

#define GROUPS 64
#define DIM    256
#define D4     (DIM / 4)      // 64 float4 per row
#define NROWS  1048576
#define CAP    20480          // per-group perm capacity (mean 16384, +32 sigma)
#define CPG    37             // chunks per group: 64*37 = 2368 = 592*4 items
#define NITEMS (GROUPS * CPG)
#define MCTA   592            // 148 SMs * 4 resident CTAs -> perfect balance
#define SCTA   148
#define CHUNK  ((NROWS + SCTA - 1) / SCTA)   // 7086
#define TPB    256
#define U      4              // quad-row unroll

// ---------------- global scratch (no allocation allowed) ----------------
__device__ int      gPerm[GROUPS * CAP];     // binned row indices
__device__ int      gOffset[GROUPS];         // scatter cursors / final counts
__device__ unsigned gMaxU[GROUPS * DIM];
__device__ unsigned gMinU[GROUPS * DIM];
__device__ float    gSum [GROUPS * DIM];

// monotonic float<->uint encoding (order-preserving over all floats)
__device__ __forceinline__ unsigned enc(float v) {
    int i = __float_as_int(v);
    return (i >= 0) ? ((unsigned)i | 0x80000000u) : ~(unsigned)i;
}
__device__ __forceinline__ float dec(unsigned u) {
    return (u & 0x80000000u) ? __int_as_float((int)(u ^ 0x80000000u))
                             : __int_as_float((int)~u);
}

// ---------------- kernel 0: reset scratch (graph replays) --------------
__global__ void k_init() {
    int i = blockIdx.x * blockDim.x + threadIdx.x;
    if (i < GROUPS * DIM) {
        gMaxU[i] = 0u;              // enc(-inf) = 0x007FFFFF, 0 never survives
        gMinU[i] = 0xFFFFFFFFu;
        gSum [i] = 0.0f;
    }
    if (i < GROUPS) gOffset[i] = i * CAP;
}

// ---------------- kernel 1: counting-sort scatter ----------------------
__global__ void __launch_bounds__(TPB) k_scatter(const int* __restrict__ gi) {
    __shared__ int sg[CHUNK];
    __shared__ int sBase[GROUPS];
    __shared__ int sCur[GROUPS];

    const int tid   = threadIdx.x;
    const int start = blockIdx.x * CHUNK;
    const int n     = min(CHUNK, NROWS - start);

    if (tid < GROUPS) sCur[tid] = 0;
    __syncthreads();

    for (int i = tid; i < n; i += TPB) {
        int g = __ldg(&gi[start + i]);
        sg[i] = g;
        atomicAdd(&sCur[g], 1);
    }
    __syncthreads();

    if (tid < GROUPS) {
        sBase[tid] = atomicAdd(&gOffset[tid], sCur[tid]);
        sCur[tid]  = 0;
    }
    __syncthreads();

    for (int i = tid; i < n; i += TPB) {
        int g = sg[i];
        int p = sBase[g] + atomicAdd(&sCur[g], 1);
        gPerm[p] = start + i;
    }
}

// ---------------- kernel 2: float4 register segment reduction ----------
// 592 persistent CTAs, each handles exactly 4 of 2368 equal work items.
// Within a CTA: sub = tid/64 (2 warps) processes one row per step (4 rows
// per iteration); thread owns float4 columns [4*lane64, +4) in registers.
__global__ void __launch_bounds__(TPB, 4) k_main(const float* __restrict__ f) {
    __shared__ float4 red[3][4][D4];            // [stat][sub][lane64] 12 KB

    const int tid    = threadIdx.x;
    const int sub    = tid >> 6;                // 0..3
    const int lane64 = tid & 63;                // float4 column index
    const float4* __restrict__ f4 = (const float4*)f;

    for (int item = blockIdx.x; item < NITEMS; item += MCTA) {
        const int g   = item / CPG;
        const int c   = item % CPG;
        const int cnt = gOffset[g] - g * CAP;
        const int per = (((cnt + CPG - 1) / CPG) + 3) & ~3;   // 4-aligned
        const int s   = c * per;
        const int e   = min(s + per, cnt);
        const int* __restrict__ perm = &gPerm[g * CAP];

        float4 aMax = make_float4(-CUDART_INF_F, -CUDART_INF_F, -CUDART_INF_F, -CUDART_INF_F);
        float4 aMin = make_float4( CUDART_INF_F,  CUDART_INF_F,  CUDART_INF_F,  CUDART_INF_F);
        float4 aSum = make_float4(0.f, 0.f, 0.f, 0.f);

        if (s < e) {
            const int nq = (e - s) >> 2;        // full row-quads
            const int r0 = s + sub;             // this sub's first row slot
            int qi = 0;
            for (; qi + U <= nq; qi += U) {
                int    r[U];
                float4 v[U];
#pragma unroll
                for (int u = 0; u < U; u++)
                    r[u] = __ldg(&perm[r0 + ((qi + u) << 2)]);
#pragma unroll
                for (int u = 0; u < U; u++)
                    v[u] = __ldg(&f4[r[u] * D4 + lane64]);
#pragma unroll
                for (int u = 0; u < U; u++) {
                    aMax.x = fmaxf(aMax.x, v[u].x); aMax.y = fmaxf(aMax.y, v[u].y);
                    aMax.z = fmaxf(aMax.z, v[u].z); aMax.w = fmaxf(aMax.w, v[u].w);
                    aMin.x = fminf(aMin.x, v[u].x); aMin.y = fminf(aMin.y, v[u].y);
                    aMin.z = fminf(aMin.z, v[u].z); aMin.w = fminf(aMin.w, v[u].w);
                    aSum.x += v[u].x; aSum.y += v[u].y;
                    aSum.z += v[u].z; aSum.w += v[u].w;
                }
            }
            for (; qi < nq; ++qi) {
                int    r = __ldg(&perm[r0 + (qi << 2)]);
                float4 v = __ldg(&f4[r * D4 + lane64]);
                aMax.x = fmaxf(aMax.x, v.x); aMax.y = fmaxf(aMax.y, v.y);
                aMax.z = fmaxf(aMax.z, v.z); aMax.w = fmaxf(aMax.w, v.w);
                aMin.x = fminf(aMin.x, v.x); aMin.y = fminf(aMin.y, v.y);
                aMin.z = fminf(aMin.z, v.z); aMin.w = fminf(aMin.w, v.w);
                aSum.x += v.x; aSum.y += v.y; aSum.z += v.z; aSum.w += v.w;
            }
            // tail rows ( < 4 )
            const int rowIdx = s + (nq << 2) + sub;
            if (rowIdx < e) {
                int    r = __ldg(&perm[rowIdx]);
                float4 v = __ldg(&f4[r * D4 + lane64]);
                aMax.x = fmaxf(aMax.x, v.x); aMax.y = fmaxf(aMax.y, v.y);
                aMax.z = fmaxf(aMax.z, v.z); aMax.w = fmaxf(aMax.w, v.w);
                aMin.x = fminf(aMin.x, v.x); aMin.y = fminf(aMin.y, v.y);
                aMin.z = fminf(aMin.z, v.z); aMin.w = fminf(aMin.w, v.w);
                aSum.x += v.x; aSum.y += v.y; aSum.z += v.z; aSum.w += v.w;
            }
        }

        // CTA-level merge of the 4 sub partials, then global atomics
        red[0][sub][lane64] = aMax;
        red[1][sub][lane64] = aMin;
        red[2][sub][lane64] = aSum;
        __syncthreads();

        const int base = g * DIM + lane64 * 4;
        if (sub == 0) {
            float4 a = red[0][0][lane64], b = red[0][1][lane64];
            float4 c2 = red[0][2][lane64], d = red[0][3][lane64];
            atomicMax(&gMaxU[base + 0], enc(fmaxf(fmaxf(a.x, b.x), fmaxf(c2.x, d.x))));
            atomicMax(&gMaxU[base + 1], enc(fmaxf(fmaxf(a.y, b.y), fmaxf(c2.y, d.y))));
            atomicMax(&gMaxU[base + 2], enc(fmaxf(fmaxf(a.z, b.z), fmaxf(c2.z, d.z))));
            atomicMax(&gMaxU[base + 3], enc(fmaxf(fmaxf(a.w, b.w), fmaxf(c2.w, d.w))));
        } else if (sub == 1) {
            float4 a = red[1][0][lane64], b = red[1][1][lane64];
            float4 c2 = red[1][2][lane64], d = red[1][3][lane64];
            atomicMin(&gMinU[base + 0], enc(fminf(fminf(a.x, b.x), fminf(c2.x, d.x))));
            atomicMin(&gMinU[base + 1], enc(fminf(fminf(a.y, b.y), fminf(c2.y, d.y))));
            atomicMin(&gMinU[base + 2], enc(fminf(fminf(a.z, b.z), fminf(c2.z, d.z))));
            atomicMin(&gMinU[base + 3], enc(fminf(fminf(a.w, b.w), fminf(c2.w, d.w))));
        } else if (sub == 2) {
            float4 a = red[2][0][lane64], b = red[2][1][lane64];
            float4 c2 = red[2][2][lane64], d = red[2][3][lane64];
            atomicAdd(&gSum[base + 0], (a.x + b.x) + (c2.x + d.x));
            atomicAdd(&gSum[base + 1], (a.y + b.y) + (c2.y + d.y));
            atomicAdd(&gSum[base + 2], (a.z + b.z) + (c2.z + d.z));
            atomicAdd(&gSum[base + 3], (a.w + b.w) + (c2.w + d.w));
        }
        __syncthreads();   // red reused next item
    }
}

// ---------------- kernel 3: finalize [G, 768] = [max || min || mean] ----
__global__ void k_final(float* __restrict__ out) {
    const int g = blockIdx.x;
    const int c = threadIdx.x;
    const int i = g * DIM + c;
    const float cnt = (float)(gOffset[g] - g * CAP);
    out[g * 3 * DIM + c]           = dec(gMaxU[i]);
    out[g * 3 * DIM + DIM + c]     = dec(gMinU[i]);
    out[g * 3 * DIM + 2 * DIM + c] = gSum[i] / cnt;
}

extern "C" void kernel_launch(void* const* d_in, const int* in_sizes, int n_in,
                              void* d_out, int out_size) {
    const float* f  = (const float*)d_in[0];   // features [N, D] f32
    const int*   gi = (const int*)d_in[1];     // group_index [N] i32
    float* out = (float*)d_out;                // [64, 768] f32

    k_init   <<<(GROUPS * DIM + 255) / 256, 256>>>();
    k_scatter<<<SCTA, TPB>>>(gi);
    k_main   <<<MCTA, TPB>>>(f);
    k_final  <<<GROUPS, DIM>>>(out);
}